// round 13
// baseline (speedup 1.0000x reference)
#include <cuda_runtime.h>

// RITS recurrence v12: 128 CTAs x 512 threads, 2 samples/CTA, 3 barriers/step.
//  16 warps/SM (4/SMSP) for latency hiding; ALL reductions in-warp (shfl);
//  zero partial-sum smem traffic; all LDS patterns conflict-free by 16B-slot
//  audit. W_lstm+U fully register-resident at 48 ull/thread (fits 128-reg cap).
//  P1 (g,kq,j): h@W_hist | d@W_gh, k-quarters in lane-quads, shfl 1,2.
//  P2 (j,ke):   z_hat (8-row) + beta (16-row) per thread, shfl 1,2,4.
//  P3 (j,g,kh): fused [cc|m|hdec] @ [W_lstm;U] column-half, gate butterfly.

#define TT 512
#define NIMP (256L * 3 * 512 * 64)
typedef unsigned long long ull;
typedef ulonglong2 ull2;

#define FMA2(acc, a, b) \
    asm("fma.rn.f32x2 %0, %1, %2, %0;" : "+l"(acc) : "l"(a), "l"(b))

__device__ __forceinline__ ull pk2(float x, float y) {
    ull r; asm("mov.b64 %0, {%1, %2};" : "=l"(r) : "f"(x), "f"(y)); return r;
}
__device__ __forceinline__ float fsum(ull v) {
    float2 r; asm("mov.b64 {%0, %1}, %2;" : "=f"(r.x), "=f"(r.y) : "l"(v));
    return r.x + r.y;
}
__device__ __forceinline__ float sigf(float x) { return 1.f / (1.f + __expf(-x)); }

// chunked layouts (stride in floats; all chunk bases land on distinct 16B slots)
#define CH20(r) (((r) >> 4) * 20 + ((r) & 15))   // 16-row chunks, h / d arrays
#define CH12(r) (((r) >> 3) * 12 + ((r) & 7))    // 8-row chunks, xc array

__global__ __launch_bounds__(512, 1) void rits_kernel(
    const float* __restrict__ inputs,
    const float* __restrict__ W_hist, const float* __restrict__ b_hist,
    const float* __restrict__ W_feat, const float* __restrict__ b_feat,
    const float* __restrict__ W_gx,   const float* __restrict__ b_gx,
    const float* __restrict__ W_gh,   const float* __restrict__ b_gh,
    const float* __restrict__ W_beta, const float* __restrict__ b_beta,
    const float* __restrict__ W_lstm, const float* __restrict__ U_lstm,
    const float* __restrict__ b_lstm,
    const float* __restrict__ W_out,  const float* __restrict__ b_out,
    float* __restrict__ out)
{
    extern __shared__ __align__(16) float sm[];
    float* sW1  = sm;              // 8192  P1 slab: warps 0-7 W_hist, 8-15 W_gh
    float* sWf  = sW1 + 8192;      // 4096  P2 W_feat_c slab
    float* sWb  = sWf + 4096;      // 8192  P2 W_beta slab
    float* sWgx = sWb + 8192;      // 64
    float* sbh  = sWgx + 64;
    float* sbf  = sbh  + 64;
    float* sbgx = sbf  + 64;
    float* sbb  = sbgx + 64;
    float* sbgh = sbb  + 64;
    float* sbl  = sbgh + 64;       // 256
    float* hC   = sbl  + 256;      // 160  h in CH20 chunks [s*80 + CH20(j)]
    float* cS   = hC   + 160;      // 128  [s*64+j]
    float* xhat = cS   + 128;      // 128  [s*64+j]
    float* xcL  = xhat + 128;      // 192  xc in CH12 chunks [s*96 + CH12(j)]
    float* gm   = xcL  + 192;      // 320  [gx(0-63)|m(64-127)] CH20 [s*160+..]
    float* aC   = gm   + 320;      // 416  [cc|m|hdec] 2 chunks of 96, stride 104
    float* inb  = aC   + 416;      // 2*416: x[128] m[128] d CH20 [2*80]

    const int tid  = threadIdx.x;
    const int bid  = blockIdx.x;
    const int lane = tid & 31;
    const int w    = tid >> 5;

    // ---- P1 slab: ((w*4+i)*32+lane) float4 = rows kq*16+4i..+3 of col j ----
    for (int idx = tid; idx < 2048; idx += 512) {
        int w16 = idx >> 7, i = (idx >> 5) & 3, l = idx & 31;
        int j = (w16 & 7) * 8 + (l >> 2), kq = l & 3, r = kq * 16 + 4 * i;
        const float* M = (w16 >> 3) ? W_gh : W_hist;
        ((float4*)sW1)[idx] = make_float4(M[r*64+j], M[(r+1)*64+j],
                                          M[(r+2)*64+j], M[(r+3)*64+j]);
    }
    // ---- P2 W_feat_c slab: ((w*2+i)*32+l), rows ke*8+4i, col j=w*4+(l>>3) ----
    for (int idx = tid; idx < 1024; idx += 512) {
        int ww = idx >> 6, i = (idx >> 5) & 1, l = idx & 31;
        int j = ww * 4 + (l >> 3), ke = l & 7, r = ke * 8 + 4 * i;
        float4 v;
        v.x = (r     == j) ? 0.f : W_feat[r*64+j];
        v.y = (r + 1 == j) ? 0.f : W_feat[(r+1)*64+j];
        v.z = (r + 2 == j) ? 0.f : W_feat[(r+2)*64+j];
        v.w = (r + 3 == j) ? 0.f : W_feat[(r+3)*64+j];
        ((float4*)sWf)[idx] = v;
    }
    // ---- P2 W_beta slab: ((w*4+i)*32+l), rows ke*16+4i ----
    for (int idx = tid; idx < 2048; idx += 512) {
        int ww = idx >> 7, i = (idx >> 5) & 3, l = idx & 31;
        int j = ww * 4 + (l >> 3), ke = l & 7, r = ke * 16 + 4 * i;
        ((float4*)sWb)[idx] = make_float4(W_beta[r*64+j], W_beta[(r+1)*64+j],
                                          W_beta[(r+2)*64+j], W_beta[(r+3)*64+j]);
    }
    if (tid < 64) {
        sWgx[tid] = W_gx[tid * 64 + tid];
        sbh[tid]  = b_hist[tid];
        sbf[tid]  = b_feat[tid];
        sbgx[tid] = b_gx[tid];
        sbb[tid]  = b_beta[tid];
        sbgh[tid] = b_gh[tid];
    }
    if (tid < 256) sbl[tid] = b_lstm[tid];
    if (tid < 160) hC[tid] = 0.f;
    if (tid < 128) cS[tid] = 0.f;

    // ---- P3 register weights: lane = jl3*8 + g*2 + kh ----
    const int khP = lane & 1;
    const int gP  = (lane >> 1) & 3;
    const int jP3 = w * 4 + (lane >> 3);
    const int colP = gP * 64 + jP3;
    ull wP[48];                 // fused rows [W_lstm 0-127 | U 0-63], half khP
#pragma unroll
    for (int q = 0; q < 48; q++) {
        int r0 = khP * 96 + 2 * q, r1 = r0 + 1;
        float a0 = (r0 < 128) ? W_lstm[r0*256 + colP] : U_lstm[(r0-128)*256 + colP];
        float a1 = (r1 < 128) ? W_lstm[r1*256 + colP] : U_lstm[(r1-128)*256 + colP];
        wP[q] = pk2(a0, a1);
    }

    // ---- decompositions ----
    const int gA  = w >> 3;                   // P1: warps 0-7 x_hat, 8-15 gamma_h
    const int jA  = (w & 7) * 8 + (lane >> 2);
    const int kqA = lane & 3;
    const int jB  = w * 4 + (lane >> 3);      // P2
    const int keB = lane & 7;

    // ---- input loader (threads 0..191) ----
    const int ls = tid / 96;
    const int lr = tid % 96;
    const int lc = lr / 32;                   // 0=x 1=m 2=d
    const int ll = lr % 32;
    const long lbase = ((long)(2 * bid + ls) * 3 + lc) * TT * 64;
    const int loff = (lc < 2) ? lc * 128 + ls * 64 + 2 * ll
                              : 256 + ls * 80 + CH20(2 * ll);
    if (tid < 192)
        *(float2*)&inb[loff] = *(const float2*)&inputs[lbase + 2 * ll];

    __syncthreads();

    int p = 0;
    for (int t = 0; t < TT; t++) {
        float* bufA = inb + p * 416;

        float2 pf = make_float2(0.f, 0.f);
        if (tid < 192 && t + 1 < TT)
            pf = *(const float2*)&inputs[lbase + (long)(t + 1) * 64 + 2 * ll];

        // ===== P1: x_hat pre (h@W_hist, g=0) | gamma_h pre (d@W_gh, g=1) =====
        {
            const float* act = gA ? (bufA + 256) : hC;     // CH20 chunks
            ull a0 = 0, a1 = 0;
#pragma unroll
            for (int i = 0; i < 4; i++) {
                ull2 x0 = *(const ull2*)&act[kqA * 20 + 4 * i];
                ull2 x1 = *(const ull2*)&act[80 + kqA * 20 + 4 * i];
                ull2 wv = *(const ull2*)&sW1[((w * 4 + i) * 32 + lane) * 4];
                FMA2(a0, wv.x, x0.x); FMA2(a0, wv.y, x0.y);
                FMA2(a1, wv.x, x1.x); FMA2(a1, wv.y, x1.y);
            }
            float v0 = fsum(a0), v1 = fsum(a1);
#pragma unroll
            for (int off = 1; off <= 2; off <<= 1) {
                v0 += __shfl_xor_sync(0xffffffffu, v0, off);
                v1 += __shfl_xor_sync(0xffffffffu, v1, off);
            }
            if (kqA < 2) {
                int s = kqA, j = jA;
                float vE = s ? v1 : v0;
                if (gA == 0) {
                    float xh = vE + sbh[j];
                    xhat[s * 64 + j] = xh;
                    float x = bufA[s * 64 + j], m = bufA[128 + s * 64 + j];
                    float d = bufA[256 + s * 80 + CH20(j)];
                    xcL[s * 96 + CH12(j)] = m * x + (1.f - m) * xh;
                    gm[s * 160 + CH20(j)] =
                        __expf(-fmaxf(d * sWgx[j] + sbgx[j], 0.f));
                    gm[s * 160 + CH20(64 + j)] = m;
                    out[(((long)(2 * bid + s) * 3 + 0) * TT + t) * 64 + j] = xh;
                } else {
                    float gh = __expf(-fmaxf(vE + sbgh[j], 0.f));
                    aC[s * 208 + 136 + j] = hC[s * 80 + CH20(j)] * gh;  // hdec
                }
            }
        }
        __syncthreads();

        // ===== P2: z_hat (xc@W_feat_c) + beta ([gx;m]@W_beta) =====
        {
            ull z0 = 0, z1 = 0, b0 = 0, b1 = 0;
#pragma unroll
            for (int i = 0; i < 2; i++) {                 // z: 8 rows
                ull2 x0 = *(const ull2*)&xcL[keB * 12 + 4 * i];
                ull2 x1 = *(const ull2*)&xcL[96 + keB * 12 + 4 * i];
                ull2 wv = *(const ull2*)&sWf[((w * 2 + i) * 32 + lane) * 4];
                FMA2(z0, wv.x, x0.x); FMA2(z0, wv.y, x0.y);
                FMA2(z1, wv.x, x1.x); FMA2(z1, wv.y, x1.y);
            }
#pragma unroll
            for (int i = 0; i < 4; i++) {                 // beta: 16 rows
                ull2 x0 = *(const ull2*)&gm[keB * 20 + 4 * i];
                ull2 x1 = *(const ull2*)&gm[160 + keB * 20 + 4 * i];
                ull2 wv = *(const ull2*)&sWb[((w * 4 + i) * 32 + lane) * 4];
                FMA2(b0, wv.x, x0.x); FMA2(b0, wv.y, x0.y);
                FMA2(b1, wv.x, x1.x); FMA2(b1, wv.y, x1.y);
            }
            float zv0 = fsum(z0), zv1 = fsum(z1);
            float bv0 = fsum(b0), bv1 = fsum(b1);
#pragma unroll
            for (int off = 1; off <= 4; off <<= 1) {
                zv0 += __shfl_xor_sync(0xffffffffu, zv0, off);
                zv1 += __shfl_xor_sync(0xffffffffu, zv1, off);
                bv0 += __shfl_xor_sync(0xffffffffu, bv0, off);
                bv1 += __shfl_xor_sync(0xffffffffu, bv1, off);
            }
            if (keB == 0) {
                int j = jB;
                float zh0 = zv0 + sbf[j], zh1 = zv1 + sbf[j];
                float be0 = sigf(bv0 + sbb[j]);
                float be1 = sigf(bv1 + sbb[j]);
                float ch0 = be0 * zh0 + (1.f - be0) * xhat[j];
                float ch1 = be1 * zh1 + (1.f - be1) * xhat[64 + j];
                float x0 = bufA[j],      m0 = bufA[128 + j];
                float x1 = bufA[64 + j], m1 = bufA[192 + j];
                aC[j]       = m0 * x0 + (1.f - m0) * ch0;           // cc s0
                aC[208 + j] = m1 * x1 + (1.f - m1) * ch1;           // cc s1
                int mo = (j < 32) ? (64 + j) : (72 + j);            // m row 64+j
                aC[mo]       = m0;
                aC[208 + mo] = m1;
                long n0 = 2 * bid, n1 = n0 + 1;
                out[((n0 * 3 + 1) * (long)TT + t) * 64 + j] = zh0;
                out[((n1 * 3 + 1) * (long)TT + t) * 64 + j] = zh1;
                out[((n0 * 3 + 2) * (long)TT + t) * 64 + j] = ch0;
                out[((n1 * 3 + 2) * (long)TT + t) * 64 + j] = ch1;
            }
        }
        __syncthreads();

        // ===== P3: z[col] = [cc|m|hdec] @ [W_lstm;U] half-k + LSTM =====
        {
            ull a0a = 0, a0b = 0, a1a = 0, a1b = 0;
            const float* c0 = aC + khP * 104;
            const float* c1 = aC + 208 + khP * 104;
#pragma unroll
            for (int i = 0; i < 24; i++) {
                ull2 L0 = *(const ull2*)&c0[4 * i];
                ull2 L1 = *(const ull2*)&c1[4 * i];
                FMA2(a0a, wP[2*i], L0.x); FMA2(a0b, wP[2*i+1], L0.y);
                FMA2(a1a, wP[2*i], L1.x); FMA2(a1b, wP[2*i+1], L1.y);
            }
            float z0 = fsum(a0a) + fsum(a0b);
            float z1 = fsum(a1a) + fsum(a1b);
            z0 += __shfl_xor_sync(0xffffffffu, z0, 1);     // kh reduce
            z1 += __shfl_xor_sync(0xffffffffu, z1, 1);
            float bl = sbl[colP];
            z0 += bl; z1 += bl;
            float f0 = __shfl_xor_sync(0xffffffffu, z0, 2);   // gate g^1
            float f1 = __shfl_xor_sync(0xffffffffu, z1, 2);
            float g0 = __shfl_xor_sync(0xffffffffu, z0, 4);   // gate g^2
            float g1 = __shfl_xor_sync(0xffffffffu, z1, 4);
            float o0 = __shfl_xor_sync(0xffffffffu, f0, 4);   // gate g^3
            float o1 = __shfl_xor_sync(0xffffffffu, f1, 4);
            if ((lane & 7) == 0) {                           // g=0 (i), kh=0
                int j = jP3;
                float cn0 = sigf(f0) * cS[j]      + sigf(z0) * tanhf(g0);
                float cn1 = sigf(f1) * cS[64 + j] + sigf(z1) * tanhf(g1);
                cS[j]      = cn0;
                cS[64 + j] = cn1;
                hC[CH20(j)]      = sigf(o0) * tanhf(cn0);
                hC[80 + CH20(j)] = sigf(o1) * tanhf(cn1);
            }
        }
        if (tid < 192 && t + 1 < TT)
            *(float2*)&inb[(p ^ 1) * 416 + loff] = pf;
        p ^= 1;
        __syncthreads();
    }

    // ===== predictions: sigmoid(h_last @ W_out + b_out) =====
    if (tid < 64) {
        int s = tid >> 5, l = tid & 31;
        float v = hC[s * 80 + CH20(l)] * W_out[l]
                + hC[s * 80 + CH20(l + 32)] * W_out[l + 32];
#pragma unroll
        for (int off = 16; off; off >>= 1)
            v += __shfl_down_sync(0xffffffffu, v, off);
        if (l == 0)
            out[NIMP + 2 * bid + s] = 1.f / (1.f + __expf(-(v + b_out[0])));
    }
}

extern "C" void kernel_launch(void* const* d_in, const int* in_sizes, int n_in,
                              void* d_out, int out_size)
{
    const float* inputs = (const float*)d_in[0];
    const float* W_hist = (const float*)d_in[1];
    const float* b_hist = (const float*)d_in[2];
    const float* W_feat = (const float*)d_in[3];
    const float* b_feat = (const float*)d_in[4];
    const float* W_gx   = (const float*)d_in[5];
    const float* b_gx   = (const float*)d_in[6];
    const float* W_gh   = (const float*)d_in[7];
    const float* b_gh   = (const float*)d_in[8];
    const float* W_beta = (const float*)d_in[9];
    const float* b_beta = (const float*)d_in[10];
    const float* W_lstm = (const float*)d_in[11];
    const float* U_lstm = (const float*)d_in[12];
    const float* b_lstm = (const float*)d_in[13];
    const float* W_out  = (const float*)d_in[14];
    const float* b_out  = (const float*)d_in[15];

    const int smem_bytes = 23296 * (int)sizeof(float);   // 93,184 B
    cudaFuncSetAttribute(rits_kernel,
                         cudaFuncAttributeMaxDynamicSharedMemorySize, smem_bytes);

    rits_kernel<<<128, 512, smem_bytes>>>(
        inputs, W_hist, b_hist, W_feat, b_feat, W_gx, b_gx, W_gh, b_gh,
        W_beta, b_beta, W_lstm, U_lstm, b_lstm, W_out, b_out,
        (float*)d_out);
}

// round 15
// speedup vs baseline: 1.4235x; 1.4235x over previous
#include <cuda_runtime.h>
#include <cuda_bf16.h>

// RITS recurrence v14 = round-3 v2 + phase-C 4-accumulator split,
// with the v13 smem-map bug fixed (pA sized 512, allocation = true footprint).

#define TT 512
#define NIMP (256L * 3 * 512 * 64)
typedef unsigned long long ull;

#define FMA2(acc, a, b) \
    asm("fma.rn.f32x2 %0, %1, %2, %0;" : "+l"(acc) : "l"(a), "l"(b))

__device__ __forceinline__ ull pk2(float x, float y) {
    ull r; asm("mov.b64 %0, {%1, %2};" : "=l"(r) : "f"(x), "f"(y)); return r;
}
__device__ __forceinline__ float2 upk(ull v) {
    float2 r; asm("mov.b64 {%0, %1}, %2;" : "=f"(r.x), "=f"(r.y) : "l"(v)); return r;
}

__global__ __launch_bounds__(256, 1) void rits_kernel(
    const float* __restrict__ inputs,
    const float* __restrict__ W_hist, const float* __restrict__ b_hist,
    const float* __restrict__ W_feat, const float* __restrict__ b_feat,
    const float* __restrict__ W_gx,   const float* __restrict__ b_gx,
    const float* __restrict__ W_gh,   const float* __restrict__ b_gh,
    const float* __restrict__ W_beta, const float* __restrict__ b_beta,
    const float* __restrict__ W_lstm, const float* __restrict__ U_lstm,
    const float* __restrict__ b_lstm,
    const float* __restrict__ W_out,  const float* __restrict__ b_out,
    float* __restrict__ out)
{
    extern __shared__ __align__(16) float sm[];
    float* sWh2  = sm;             // 4096   [0, 4096)
    float* sWf2  = sWh2  + 4096;   // 4096   [4096, 8192)
    float* sWb2  = sWf2  + 4096;   // 8192   [8192, 16384)
    float* sWgh2 = sWb2  + 8192;   // 4096   [16384, 20480)
    float* sWgx  = sWgh2 + 4096;   // 64
    float* sbh   = sWgx + 64;      // 64
    float* sbf   = sbh  + 64;      // 64
    float* sbgx  = sbf  + 64;      // 64
    float* sbb   = sbgx + 64;      // 64
    float* sbgh  = sbb  + 64;      // 64    -> 20864
    float* sbl   = sbgh + 64;      // 256   -> 21120
    float* hS    = sbl  + 256;     // 128
    float* cS    = hS   + 128;     // 128
    float* hdec  = cS   + 128;     // 128
    float* xhat  = hdec + 128;     // 128
    float* ccm   = xhat + 128;     // 256
    float* actB  = ccm  + 256;     // 384   -> 22272
    float* pA    = actB + 384;     // 512   -> 22784  (max index used: 511)
    float* pz    = pA   + 512;     // 256   -> 23040
    float* pb    = pz   + 256;     // 512   -> 23552
    float* zbuf  = pb   + 512;     // 512   -> 24064
    float* inb   = zbuf + 512;     // 768   -> 24832  TOTAL
    // total = 24832 floats = 99,328 bytes (allocated below)

    const int tid = threadIdx.x;
    const int bid = blockIdx.x;

    // ---- pack smem weights: {W[2q][j], W[2q+1][j]} at float offset (q*64+j)*2
    for (int i = tid; i < 2048; i += 256) {
        int q = i >> 6, j = i & 63;
        *(float2*)&sWh2[i * 2]  = make_float2(W_hist[(2*q)*64 + j], W_hist[(2*q+1)*64 + j]);
        *(float2*)&sWgh2[i * 2] = make_float2(W_gh[(2*q)*64 + j],   W_gh[(2*q+1)*64 + j]);
    }
    for (int i = tid; i < 2048; i += 256) {
        int q = i >> 6, j = i & 63;
        float a = (2*q     == j) ? 0.f : W_feat[(2*q)*64 + j];
        float b = (2*q + 1 == j) ? 0.f : W_feat[(2*q+1)*64 + j];
        *(float2*)&sWf2[i * 2] = make_float2(a, b);
    }
    for (int i = tid; i < 4096; i += 256) {
        int q = i >> 6, j = i & 63;
        *(float2*)&sWb2[i * 2] = make_float2(W_beta[(2*q)*64 + j], W_beta[(2*q+1)*64 + j]);
    }
    if (tid < 64) {
        sWgx[tid] = W_gx[tid * 64 + tid];
        sbh[tid]  = b_hist[tid];
        sbf[tid]  = b_feat[tid];
        sbgx[tid] = b_gx[tid];
        sbb[tid]  = b_beta[tid];
        sbgh[tid] = b_gh[tid];
    }
    sbl[tid] = b_lstm[tid];
    if (tid < 128) { hS[tid] = 0.f; cS[tid] = 0.f; }

    // ---- register-stationary weights: column `tid`, packed over k pairs ----
    ull wl2[64], ul2[32];
#pragma unroll
    for (int q = 0; q < 64; q++)
        wl2[q] = pk2(W_lstm[(2*q)*256 + tid], W_lstm[(2*q+1)*256 + tid]);
#pragma unroll
    for (int q = 0; q < 32; q++)
        ul2[q] = pk2(U_lstm[(2*q)*256 + tid], U_lstm[(2*q+1)*256 + tid]);

    // ---- input loader mapping (threads 0..191) ----
    const int ls = tid / 96;            // sample
    const int lr = tid % 96;
    const int lc = lr / 32;             // channel 0=x 1=m 2=d
    const int ll = lr % 32;
    const long lbase = ((long)(2 * bid + ls) * 3 + lc) * TT * 64;

    if (tid < 192) {
        float2 v = *(const float2*)&inputs[lbase + 2 * ll];
        *(float2*)&inb[lc * 128 + ls * 64 + 2 * ll] = v;
    }
    __syncthreads();

    const int g  = tid >> 7;            // phase A half
    const int kh = (tid >> 6) & 1;      // phase A k-half
    const int jA = tid & 63;
    const int u  = tid >> 6;            // phase B quarter
    const int jB = tid & 63;

    int p = 0;
    for (int t = 0; t < TT; t++) {
        float* bufc = inb + p * 384;

        float2 pf = make_float2(0.f, 0.f);
        if (tid < 192 && t + 1 < TT)
            pf = *(const float2*)&inputs[lbase + (long)(t + 1) * 64 + 2 * ll];

        // ===== Phase A: x_hat pre (h@W_hist) / gamma_h pre (d@W_gh) =====
        {
            const float* act = g ? (bufc + 256) : hS;
            const float* W   = g ? sWgh2 : sWh2;
            ull acc0 = 0, acc1 = 0;
#pragma unroll
            for (int i = 0; i < 8; i++) {
                int k = kh * 32 + 4 * i, q = k >> 1;
                ulonglong2 a0 = *(const ulonglong2*)&act[k];
                ulonglong2 a1 = *(const ulonglong2*)&act[64 + k];
                ull wa = *(const ull*)&W[(q * 64 + jA) * 2];
                ull wb = *(const ull*)&W[((q + 1) * 64 + jA) * 2];
                FMA2(acc0, wa, a0.x); FMA2(acc0, wb, a0.y);
                FMA2(acc1, wa, a1.x); FMA2(acc1, wb, a1.y);
            }
            float2 r0 = upk(acc0), r1 = upk(acc1);
            pA[(g * 2 + kh) * 128 + jA]      = r0.x + r0.y;
            pA[(g * 2 + kh) * 128 + 64 + jA] = r1.x + r1.y;
        }
        __syncthreads();

        // ===== Phase A2: x_hat, x_c, gamma_x | gamma_h, h_dec =====
        {
            int r = tid & 127, s = r >> 6, j = r & 63;
            if (g == 0) {
                float v = pA[s * 64 + j] + pA[128 + s * 64 + j] + sbh[j];
                xhat[r] = v;
                float x = bufc[r], m = bufc[128 + r], d = bufc[256 + r];
                actB[s * 192 + j]       = m * x + (1.f - m) * v;
                actB[s * 192 + 64 + j]  = __expf(-fmaxf(d * sWgx[j] + sbgx[j], 0.f));
                actB[s * 192 + 128 + j] = m;
                long n = 2 * bid + s;
                out[((n * 3 + 0) * (long)TT + t) * 64 + j] = v;
            } else {
                float v = pA[256 + s * 64 + j] + pA[384 + s * 64 + j];
                float gh = __expf(-fmaxf(v + sbgh[j], 0.f));
                hdec[r] = hS[r] * gh;
            }
        }
        __syncthreads();

        // ===== Phase B: z_hat (actB[xc]) + beta pre (actB[gx|m] @ W_beta) ===
        {
            ull z0 = 0, z1 = 0, b0 = 0, b1 = 0;
            if (u < 2) {
#pragma unroll
                for (int i = 0; i < 8; i++) {            // z_hat, 32 k
                    int k = u * 32 + 4 * i, q = k >> 1;
                    ulonglong2 a0 = *(const ulonglong2*)&actB[k];
                    ulonglong2 a1 = *(const ulonglong2*)&actB[192 + k];
                    ull wa = *(const ull*)&sWf2[(q * 64 + jB) * 2];
                    ull wb = *(const ull*)&sWf2[((q + 1) * 64 + jB) * 2];
                    FMA2(z0, wa, a0.x); FMA2(z0, wb, a0.y);
                    FMA2(z1, wa, a1.x); FMA2(z1, wb, a1.y);
                }
#pragma unroll
                for (int i = 0; i < 4; i++) {            // beta, 16 k (gamma_x)
                    int k = u * 16 + 4 * i, q = k >> 1;
                    ulonglong2 a0 = *(const ulonglong2*)&actB[64 + k];
                    ulonglong2 a1 = *(const ulonglong2*)&actB[192 + 64 + k];
                    ull wa = *(const ull*)&sWb2[(q * 64 + jB) * 2];
                    ull wb = *(const ull*)&sWb2[((q + 1) * 64 + jB) * 2];
                    FMA2(b0, wa, a0.x); FMA2(b0, wb, a0.y);
                    FMA2(b1, wa, a1.x); FMA2(b1, wb, a1.y);
                }
                float2 r0 = upk(z0), r1 = upk(z1);
                pz[u * 128 + jB]      = r0.x + r0.y;
                pz[u * 128 + 64 + jB] = r1.x + r1.y;
            } else if (u == 2) {
#pragma unroll
                for (int i = 0; i < 8; i++) {            // beta, k 32..63 (gamma_x)
                    int k = 32 + 4 * i, q = k >> 1;
                    ulonglong2 a0 = *(const ulonglong2*)&actB[64 + k];
                    ulonglong2 a1 = *(const ulonglong2*)&actB[192 + 64 + k];
                    ull wa = *(const ull*)&sWb2[(q * 64 + jB) * 2];
                    ull wb = *(const ull*)&sWb2[((q + 1) * 64 + jB) * 2];
                    FMA2(b0, wa, a0.x); FMA2(b0, wb, a0.y);
                    FMA2(b1, wa, a1.x); FMA2(b1, wb, a1.y);
                }
#pragma unroll
                for (int i = 0; i < 4; i++) {            // beta, k 64..79 (m)
                    int k = 64 + 4 * i, q = k >> 1;
                    ulonglong2 a0 = *(const ulonglong2*)&actB[64 + k];
                    ulonglong2 a1 = *(const ulonglong2*)&actB[192 + 64 + k];
                    ull wa = *(const ull*)&sWb2[(q * 64 + jB) * 2];
                    ull wb = *(const ull*)&sWb2[((q + 1) * 64 + jB) * 2];
                    FMA2(b0, wa, a0.x); FMA2(b0, wb, a0.y);
                    FMA2(b1, wa, a1.x); FMA2(b1, wb, a1.y);
                }
            } else {
#pragma unroll
                for (int i = 0; i < 12; i++) {           // beta, k 80..127 (m)
                    int k = 80 + 4 * i, q = k >> 1;
                    ulonglong2 a0 = *(const ulonglong2*)&actB[64 + k];
                    ulonglong2 a1 = *(const ulonglong2*)&actB[192 + 64 + k];
                    ull wa = *(const ull*)&sWb2[(q * 64 + jB) * 2];
                    ull wb = *(const ull*)&sWb2[((q + 1) * 64 + jB) * 2];
                    FMA2(b0, wa, a0.x); FMA2(b0, wb, a0.y);
                    FMA2(b1, wa, a1.x); FMA2(b1, wb, a1.y);
                }
            }
            float2 r0 = upk(b0), r1 = upk(b1);
            pb[u * 128 + jB]      = r0.x + r0.y;
            pb[u * 128 + 64 + jB] = r1.x + r1.y;
        }
        __syncthreads();

        // ===== Phase B2: beta, c_hat, c_c =====
        if (tid < 128) {
            int s = tid >> 6, j = tid & 63, r = tid;
            float zh   = pz[r] + pz[128 + r] + sbf[j];
            float bpre = pb[r] + pb[128 + r] + pb[256 + r] + pb[384 + r] + sbb[j];
            float beta = 1.f / (1.f + __expf(-bpre));
            float xh   = xhat[r];
            float chat = beta * zh + (1.f - beta) * xh;
            float x = bufc[r], m = bufc[128 + r];
            ccm[s * 128 + j]      = m * x + (1.f - m) * chat;
            ccm[s * 128 + 64 + j] = m;
            long n = 2 * bid + s;
            out[((n * 3 + 1) * (long)TT + t) * 64 + j] = zh;
            out[((n * 3 + 2) * (long)TT + t) * 64 + j] = chat;
        }
        __syncthreads();

        // ===== Phase C: z[o] = [c_c;m]@W_lstm (regs) + h_dec@U (regs) + b ====
        // 4 accumulators (x/y streams split) -> dep chain 96 -> 48 FMA2
        {
            ull acc0 = 0, acc1 = 0, acc2 = 0, acc3 = 0;
#pragma unroll
            for (int i = 0; i < 32; i++) {
                ulonglong2 a0 = *(const ulonglong2*)&ccm[4 * i];
                ulonglong2 a1 = *(const ulonglong2*)&ccm[128 + 4 * i];
                FMA2(acc0, wl2[2*i],   a0.x); FMA2(acc2, wl2[2*i+1], a0.y);
                FMA2(acc1, wl2[2*i],   a1.x); FMA2(acc3, wl2[2*i+1], a1.y);
            }
#pragma unroll
            for (int i = 0; i < 16; i++) {
                ulonglong2 a0 = *(const ulonglong2*)&hdec[4 * i];
                ulonglong2 a1 = *(const ulonglong2*)&hdec[64 + 4 * i];
                FMA2(acc0, ul2[2*i],   a0.x); FMA2(acc2, ul2[2*i+1], a0.y);
                FMA2(acc1, ul2[2*i],   a1.x); FMA2(acc3, ul2[2*i+1], a1.y);
            }
            float2 r0 = upk(acc0), r1 = upk(acc1);
            float2 r2 = upk(acc2), r3 = upk(acc3);
            float b = sbl[tid];
            zbuf[tid]       = r0.x + r0.y + r2.x + r2.y + b;
            zbuf[256 + tid] = r1.x + r1.y + r3.x + r3.y + b;
        }
        __syncthreads();

        // ===== Phase C2: LSTM gates; commit prefetched inputs =====
        if (tid < 128) {
            int s = tid >> 6, j = tid & 63;
            const float* zs = zbuf + s * 256;
            float iv = zs[j], fv = zs[64 + j], gv = zs[128 + j], ov = zs[192 + j];
            float co = cS[tid];
            float si = 1.f / (1.f + __expf(-iv));
            float sf = 1.f / (1.f + __expf(-fv));
            float so = 1.f / (1.f + __expf(-ov));
            float cn = sf * co + si * tanhf(gv);
            cS[tid] = cn;
            hS[tid] = so * tanhf(cn);
        }
        if (tid < 192 && t + 1 < TT)
            *(float2*)&inb[(p ^ 1) * 384 + lc * 128 + ls * 64 + 2 * ll] = pf;
        p ^= 1;
        __syncthreads();
    }

    // ===== predictions: sigmoid(h_last @ W_out + b_out) =====
    if (tid < 64) {
        int s = tid >> 5, l = tid & 31;
        float v = hS[s * 64 + l] * W_out[l] + hS[s * 64 + 32 + l] * W_out[32 + l];
#pragma unroll
        for (int off = 16; off; off >>= 1)
            v += __shfl_down_sync(0xffffffffu, v, off);
        if (l == 0)
            out[NIMP + 2 * bid + s] = 1.f / (1.f + __expf(-(v + b_out[0])));
    }
}

extern "C" void kernel_launch(void* const* d_in, const int* in_sizes, int n_in,
                              void* d_out, int out_size)
{
    const float* inputs = (const float*)d_in[0];
    const float* W_hist = (const float*)d_in[1];
    const float* b_hist = (const float*)d_in[2];
    const float* W_feat = (const float*)d_in[3];
    const float* b_feat = (const float*)d_in[4];
    const float* W_gx   = (const float*)d_in[5];
    const float* b_gx   = (const float*)d_in[6];
    const float* W_gh   = (const float*)d_in[7];
    const float* b_gh   = (const float*)d_in[8];
    const float* W_beta = (const float*)d_in[9];
    const float* b_beta = (const float*)d_in[10];
    const float* W_lstm = (const float*)d_in[11];
    const float* U_lstm = (const float*)d_in[12];
    const float* b_lstm = (const float*)d_in[13];
    const float* W_out  = (const float*)d_in[14];
    const float* b_out  = (const float*)d_in[15];

    const int smem_bytes = 24832 * (int)sizeof(float);   // 99,328 B (= map total)
    cudaFuncSetAttribute(rits_kernel,
                         cudaFuncAttributeMaxDynamicSharedMemorySize, smem_bytes);

    rits_kernel<<<128, 256, smem_bytes>>>(
        inputs, W_hist, b_hist, W_feat, b_feat, W_gx, b_gx, W_gh, b_gh,
        W_beta, b_beta, W_lstm, U_lstm, b_lstm, W_out, b_out,
        (float*)d_out);
}